// round 13
// baseline (speedup 1.0000x reference)
#include <cuda_runtime.h>

#define BB 16
#define NN 2048
#define CC 256
#define RR 128
#define KK 16

// ---------------- scratch ----------------
__device__ float g_x1 [BB*RR*NN];
__device__ float g_x2 [BB*RR*NN];
__device__ float g_x2t[BB*NN*RR];
__device__ float g_z  [BB*RR*NN];
__device__ float g_zt [BB*NN*RR];
__device__ float g_lap[BB*NN*RR];
__device__ float g_t  [BB*RR*NN];
__device__ float g_y  [BB*CC*NN];
__device__ int   g_idx[BB*NN*KK];
__device__ int   g_cnt[BB*NN];
__device__ float g_s1 [5*512];
__device__ float g_s2 [5*512];
__device__ float g_wt [229376];            // k-major transposed weights

__global__ void zero_kernel() {
    for (int i = threadIdx.x; i < 5 * 512; i += 256) { g_s1[i] = 0.f; g_s2[i] = 0.f; }
}

// ---------------- weight transpose: wt[k][o] = w[o][k] ----------------------------
__device__ __forceinline__ void tr1(const float* __restrict__ in, int O, int I,
                                    float* __restrict__ out, int tid, int nth) {
    for (int x = tid; x < O * I; x += nth) {
        int o = x / I, k = x - o * I;
        out[k * O + o] = in[x];
    }
}
__global__ void __launch_bounds__(256) tw_kernel(const float* __restrict__ w1,
                                                 const float* __restrict__ fcw,
                                                 const float* __restrict__ luw,
                                                 const float* __restrict__ w2,
                                                 const float* __restrict__ w3) {
    int tid = blockIdx.x * 256 + threadIdx.x;
    int nth = gridDim.x * 256;
    tr1(w1, 128, 256, g_wt + 0,      tid, nth);
    tr1(fcw,128, 128, g_wt + 32768,  tid, nth);
    tr1(luw,128, 128, g_wt + 49152,  tid, nth);
    tr1(w2, 256, 128, g_wt + 65536,  tid, nth);
    tr1(w3, 512, 256, g_wt + 98304,  tid, nth);
}

// ---------------- kNN: bit-exact, register-resident top-16 -- DO NOT TOUCH --------
__global__ void __launch_bounds__(256) knn_kernel(const float* __restrict__ xyz,
                                                  int* __restrict__ idx) {
    int b  = blockIdx.x >> 3;
    int q0 = (blockIdx.x & 7) << 8;
    __shared__ float sx[NN], sy[NN], sxx[NN];
    const float* bx = xyz + (size_t)b * 3 * NN;
    for (int i = threadIdx.x; i < NN; i += 256) {
        float xv = bx[i], yv = bx[NN + i];
        sx[i] = xv; sy[i] = yv;
        sxx[i] = __fadd_rn(__fmul_rn(xv, xv), __fmul_rn(yv, yv));
    }
    __syncthreads();
    int q = q0 + threadIdx.x;
    float xq = sx[q], yq = sy[q];
    float xxq = sxx[q];
    float bd[KK]; int bi[KK];
#pragma unroll
    for (int i = 0; i < KK; i++) { bd[i] = 3.4e38f; bi[i] = 0; }
    for (int m = 0; m < NN; m++) {
        float inner = __fmaf_rn(yq, sy[m], __fmul_rn(xq, sx[m]));
        float d = __fadd_rn(__fsub_rn(xxq, __fmul_rn(2.0f, inner)), sxx[m]);
        if (d < bd[KK - 1]) {
            bool p[KK];
#pragma unroll
            for (int i = 0; i < KK; i++) p[i] = (d < bd[i]);
#pragma unroll
            for (int i = KK - 1; i > 0; i--) {
                bd[i] = p[i] ? (p[i - 1] ? bd[i - 1] : d) : bd[i];
                bi[i] = p[i] ? (p[i - 1] ? bi[i - 1] : m) : bi[i];
            }
            if (p[0]) { bd[0] = d; bi[0] = m; }
        }
    }
    int* o = idx + ((size_t)(b * NN + q)) * KK;
#pragma unroll
    for (int i = 0; i < KK; i++) o[i] = bi[i];
}

__global__ void __launch_bounds__(256) cnt_kernel(const int* __restrict__ idx,
                                                  int* __restrict__ cnt) {
    int b = blockIdx.x, tid = threadIdx.x;
    __shared__ int sc[NN];
    for (int i = tid; i < NN; i += 256) sc[i] = 0;
    __syncthreads();
    for (int i = tid; i < NN * 8; i += 256)
        atomicAdd(&sc[idx[((size_t)(b * NN + (i >> 3))) * KK + (i & 7)]], 1);
    __syncthreads();
    for (int i = tid; i < NN; i += 256) cnt[b * NN + i] = sc[i];
}

// Granule (16B) XOR swizzle within a 128-float row (pure layout permutation).
__device__ __forceinline__ int swzc(int c) {
    return c ^ (((c >> 5) & 1) << 2);
}

__device__ __forceinline__ void cpa16(void* dst, const void* src) {
    unsigned int d = (unsigned int)__cvta_generic_to_shared(dst);
    asm volatile("cp.async.ca.shared.global [%0], [%1], 16;" :: "r"(d), "l"(src));
}

// ---------------- B-tile register load with fused input transform -----------------
// TRANS 1: relu(bn(IN))   2: IN + relu(bn(AUX))   3: relu(bn(IN)) + AUX
template<int I, int MODE, int TRANS>
__device__ __forceinline__ void load_b(const float* __restrict__ IN,
                                       const float* __restrict__ AUX,
                                       const float* __restrict__ ssc,
                                       const float* __restrict__ ssh,
                                       int b, int q0, int tid, int kb,
                                       float4& v0, float4& v1) {
    if (MODE == 0) {
        int i = tid >> 4, q8 = (tid & 15) * 8;
        size_t off = ((size_t)(b * I + kb + i)) * 2048 + q0 + q8;
        v0 = *(const float4*)(IN + off); v1 = *(const float4*)(IN + off + 4);
        if (TRANS != 0) {
            int c = kb + i;
            float s = ssc[c], h = ssh[c];
            if (TRANS == 1) {
                v0.x = fmaxf(fmaf(v0.x, s, h), 0.f); v0.y = fmaxf(fmaf(v0.y, s, h), 0.f);
                v0.z = fmaxf(fmaf(v0.z, s, h), 0.f); v0.w = fmaxf(fmaf(v0.w, s, h), 0.f);
                v1.x = fmaxf(fmaf(v1.x, s, h), 0.f); v1.y = fmaxf(fmaf(v1.y, s, h), 0.f);
                v1.z = fmaxf(fmaf(v1.z, s, h), 0.f); v1.w = fmaxf(fmaf(v1.w, s, h), 0.f);
            } else {
                float4 a0 = *(const float4*)(AUX + off);
                float4 a1 = *(const float4*)(AUX + off + 4);
                if (TRANS == 2) {
                    v0.x += fmaxf(fmaf(a0.x, s, h), 0.f); v0.y += fmaxf(fmaf(a0.y, s, h), 0.f);
                    v0.z += fmaxf(fmaf(a0.z, s, h), 0.f); v0.w += fmaxf(fmaf(a0.w, s, h), 0.f);
                    v1.x += fmaxf(fmaf(a1.x, s, h), 0.f); v1.y += fmaxf(fmaf(a1.y, s, h), 0.f);
                    v1.z += fmaxf(fmaf(a1.z, s, h), 0.f); v1.w += fmaxf(fmaf(a1.w, s, h), 0.f);
                } else {
                    v0.x = fmaxf(fmaf(v0.x, s, h), 0.f) + a0.x; v0.y = fmaxf(fmaf(v0.y, s, h), 0.f) + a0.y;
                    v0.z = fmaxf(fmaf(v0.z, s, h), 0.f) + a0.z; v0.w = fmaxf(fmaf(v0.w, s, h), 0.f) + a0.w;
                    v1.x = fmaxf(fmaf(v1.x, s, h), 0.f) + a1.x; v1.y = fmaxf(fmaf(v1.y, s, h), 0.f) + a1.y;
                    v1.z = fmaxf(fmaf(v1.z, s, h), 0.f) + a1.z; v1.w = fmaxf(fmaf(v1.w, s, h), 0.f) + a1.w;
                }
            }
        }
    } else {
        int qq = tid >> 1, i8 = (tid & 1) * 8;
        const float* p = IN + ((size_t)(b * 2048 + q0 + qq)) * I + kb + i8;
        v0 = *(const float4*)p; v1 = *(const float4*)(p + 4);
    }
}

// ---------------- SGEMM: cp.async A (k-major Wt), FFMA2 core, fused BN ------------
// Bitwise-identical fma chains to previous rounds.
template<int O, int I, int MODE, int TRANS, int STATS, bool WT>
__global__ void __launch_bounds__(256, 2) gemm4_kernel(const float* __restrict__ IN,
                                                       const float* __restrict__ AUX,
                                                       const float* __restrict__ WTm,
                                                       const float* __restrict__ bias,
                                                       const float* __restrict__ gam,
                                                       const float* __restrict__ bet,
                                                       const float* __restrict__ P1in,
                                                       const float* __restrict__ P2in,
                                                       float Mstat,
                                                       float* __restrict__ OUT,
                                                       float* __restrict__ OUT_T,
                                                       float* __restrict__ P1,
                                                       float* __restrict__ P2,
                                                       const int* __restrict__ cnt) {
    __shared__ float sA[2][16][128];
    __shared__ float sB[2][16][128];
    __shared__ float st1[128], st2[128];
    __shared__ float ssc[256], ssh[256];
    const bool BASYNC = (MODE == 0 && TRANS == 0);
    int b  = blockIdx.z;
    int q0 = blockIdx.x * 128;
    int o0 = blockIdx.y * 128;
    int tid = threadIdx.x;
    int w = tid >> 5, lane = tid & 31;
    int ty = (w >> 1) * 4 + (lane >> 3);
    int tx = (w & 1) * 8 + (lane & 7);

    if (TRANS != 0) {                       // recompute input-BN consts per block
        for (int c = tid; c < I; c += 256) {
            float mean = P1in[c] / Mstat;
            float var  = P2in[c] / Mstat - mean * mean;
            float s = gam[c] * rsqrtf(var + 1e-5f);
            ssc[c] = s; ssh[c] = bet[c] - mean * s;
        }
        __syncthreads();
    }

    const int rowS = tid >> 4, c8 = (tid & 15) * 8;      // staging coords
    const int qqR = tid >> 1, i8R = (tid & 1) * 8;       // MODE2 register path
    const int qqRs = swzc(qqR & ~3) + (qqR & 3);
    float4 rB0, rB1;

    // ---- prologue: tile 0 ----
    {
        const float* srcA = WTm + (size_t)rowS * O + o0 + c8;
        cpa16(&sA[0][rowS][swzc(c8)], srcA);
        cpa16(&sA[0][rowS][swzc(c8 + 4)], srcA + 4);
        if (BASYNC) {
            const float* srcB = IN + ((size_t)(b * I + rowS)) * 2048 + q0 + c8;
            cpa16(&sB[0][rowS][swzc(c8)], srcB);
            cpa16(&sB[0][rowS][swzc(c8 + 4)], srcB + 4);
        } else {
            load_b<I, MODE, TRANS>(IN, AUX, ssc, ssh, b, q0, tid, 0, rB0, rB1);
            if (MODE == 0) {
                *(float4*)&sB[0][rowS][swzc(c8)] = rB0;
                *(float4*)&sB[0][rowS][swzc(c8 + 4)] = rB1;
            } else {
                float bv[8] = {rB0.x, rB0.y, rB0.z, rB0.w, rB1.x, rB1.y, rB1.z, rB1.w};
#pragma unroll
                for (int t = 0; t < 8; t++) sB[0][i8R + t][qqRs] = bv[t];
            }
        }
        asm volatile("cp.async.commit_group;");
        asm volatile("cp.async.wait_group 0;");
    }
    __syncthreads();

    unsigned long long acc2[8][4];
#pragma unroll
    for (int i = 0; i < 8; i++)
#pragma unroll
        for (int j = 0; j < 4; j++) acc2[i][j] = 0ull;

    const int tyc0 = swzc(ty * 8), tyc1 = swzc(ty * 8 + 4);
    const int txc0 = swzc(tx * 8), txc1 = swzc(tx * 8 + 4);

    int buf = 0;
    for (int kb = 0; kb < I; kb += 16) {
        bool more = (kb + 16) < I;
        if (more) {
            int kn = kb + 16, nb = buf ^ 1;
            const float* srcA = WTm + (size_t)(kn + rowS) * O + o0 + c8;
            cpa16(&sA[nb][rowS][swzc(c8)], srcA);
            cpa16(&sA[nb][rowS][swzc(c8 + 4)], srcA + 4);
            if (BASYNC) {
                const float* srcB = IN + ((size_t)(b * I + kn + rowS)) * 2048 + q0 + c8;
                cpa16(&sB[nb][rowS][swzc(c8)], srcB);
                cpa16(&sB[nb][rowS][swzc(c8 + 4)], srcB + 4);
            } else {
                load_b<I, MODE, TRANS>(IN, AUX, ssc, ssh, b, q0, tid, kn, rB0, rB1);
            }
            asm volatile("cp.async.commit_group;");
        }
#pragma unroll
        for (int kk = 0; kk < 16; kk++) {
            float a[8];
            *(float4*)&a[0]  = *(const float4*)&sA[buf][kk][tyc0];
            *(float4*)&a[4]  = *(const float4*)&sA[buf][kk][tyc1];
            ulonglong2 bl0 = *(const ulonglong2*)&sB[buf][kk][txc0];
            ulonglong2 bl1 = *(const ulonglong2*)&sB[buf][kk][txc1];
            unsigned long long b2[4] = {bl0.x, bl0.y, bl1.x, bl1.y};
#pragma unroll
            for (int i = 0; i < 8; i++) {
                unsigned long long a2;
                unsigned int au = __float_as_uint(a[i]);
                asm("mov.b64 %0, {%1, %1};" : "=l"(a2) : "r"(au));
#pragma unroll
                for (int j = 0; j < 4; j++)
                    asm("fma.rn.f32x2 %0, %1, %2, %0;" : "+l"(acc2[i][j]) : "l"(a2), "l"(b2[j]));
            }
        }
        if (more && !BASYNC) {
            int nb = buf ^ 1;
            if (MODE == 0) {
                *(float4*)&sB[nb][rowS][swzc(c8)] = rB0;
                *(float4*)&sB[nb][rowS][swzc(c8 + 4)] = rB1;
            } else {
                float bv[8] = {rB0.x, rB0.y, rB0.z, rB0.w, rB1.x, rB1.y, rB1.z, rB1.w};
#pragma unroll
                for (int t = 0; t < 8; t++) sB[nb][i8R + t][qqRs] = bv[t];
            }
        }
        if (more) asm volatile("cp.async.wait_group 0;");
        __syncthreads();
        buf ^= 1;
    }

    float acc[8][8];
#pragma unroll
    for (int i = 0; i < 8; i++)
#pragma unroll
        for (int j = 0; j < 4; j++) {
            unsigned int lo, hi;
            asm("mov.b64 {%0, %1}, %2;" : "=r"(lo), "=r"(hi) : "l"(acc2[i][j]));
            acc[i][2 * j]     = __uint_as_float(lo);
            acc[i][2 * j + 1] = __uint_as_float(hi);
        }

    float bv[8];
#pragma unroll
    for (int i = 0; i < 8; i++) bv[i] = bias[o0 + ty * 8 + i];
#pragma unroll
    for (int i = 0; i < 8; i++) {
        float* orow = OUT + ((size_t)(b * O + o0 + ty * 8 + i)) * 2048 + q0 + tx * 8;
        float4 v0 = {acc[i][0] + bv[i], acc[i][1] + bv[i], acc[i][2] + bv[i], acc[i][3] + bv[i]};
        float4 v1 = {acc[i][4] + bv[i], acc[i][5] + bv[i], acc[i][6] + bv[i], acc[i][7] + bv[i]};
        *(float4*)orow = v0; *(float4*)(orow + 4) = v1;
    }
    if (WT) {
#pragma unroll
        for (int j = 0; j < 8; j++) {
            float* trow = OUT_T + ((size_t)(b * 2048 + q0 + tx * 8 + j)) * O + o0 + ty * 8;
            float4 v0 = {acc[0][j] + bv[0], acc[1][j] + bv[1], acc[2][j] + bv[2], acc[3][j] + bv[3]};
            float4 v1 = {acc[4][j] + bv[4], acc[5][j] + bv[5], acc[6][j] + bv[6], acc[7][j] + bv[7]};
            *(float4*)trow = v0; *(float4*)(trow + 4) = v1;
        }
    }
    if (STATS != 0) {
        if (tid < 128) { st1[tid] = 0.f; st2[tid] = 0.f; }
        __syncthreads();
        float wj[8];
#pragma unroll
        for (int j = 0; j < 8; j++)
            wj[j] = (STATS == 2) ? (float)cnt[(size_t)b * 2048 + q0 + tx * 8 + j] : 1.f;
#pragma unroll
        for (int i = 0; i < 8; i++) {
            float ls = 0.f, ls2 = 0.f;
#pragma unroll
            for (int j = 0; j < 8; j++) {
                float val = acc[i][j] + bv[i];
                float wv = wj[j] * val;
                ls += wv; ls2 = fmaf(wv, val, ls2);
            }
            atomicAdd(&st1[ty * 8 + i], ls);
            atomicAdd(&st2[ty * 8 + i], ls2);
        }
        __syncthreads();
        if (tid < 128) {
            atomicAdd(&P1[o0 + tid], st1[tid]);
            atomicAdd(&P2[o0 + tid], st2[tid]);
        }
    }
}

// ---------------- DSgroup: gather zt rows, BN+max8+ReLU -> x2, x2t ----------------
__global__ void __launch_bounds__(256) dsg_max_kernel(const float* __restrict__ zt,
                                                      const int* __restrict__ idx,
                                                      float* __restrict__ x2,
                                                      float* __restrict__ x2t,
                                                      const float* __restrict__ P1,
                                                      const float* __restrict__ P2,
                                                      const float* __restrict__ gam,
                                                      const float* __restrict__ bet,
                                                      float M) {
    int b = blockIdx.y, n0 = blockIdx.x * 32;
    int tid = threadIdx.x, w = tid >> 5, lane = tid & 31;
    __shared__ float stage[32][129];
    __shared__ float s4[RR], h4[RR];
    if (tid < RR) {
        float mean = P1[tid] / M;
        float var  = P2[tid] / M - mean * mean;
        float s = gam[tid] * rsqrtf(var + 1e-5f);
        s4[tid] = s; h4[tid] = bet[tid] - mean * s;
    }
    __syncthreads();
    float4 sc = ((const float4*)s4)[lane], sh = ((const float4*)h4)[lane];
#pragma unroll
    for (int phase = 0; phase < 4; phase++) {
        int nl = phase * 8 + w;
        int n  = n0 + nl;
        int src = 0;
        if (lane < 8) {
            int p = lane * NN + n;
            src = idx[((size_t)(b * NN + (p >> 3))) * KK + (p & 7)];
        }
        float4 m;
#pragma unroll
        for (int j = 0; j < 8; j++) {
            int s = __shfl_sync(0xffffffffu, src, j);
            float4 v = *(const float4*)(zt + ((size_t)(b * NN + s)) * RR + lane * 4);
            float4 t;
            t.x = fmaf(v.x, sc.x, sh.x); t.y = fmaf(v.y, sc.y, sh.y);
            t.z = fmaf(v.z, sc.z, sh.z); t.w = fmaf(v.w, sc.w, sh.w);
            if (j == 0) m = t;
            else {
                m.x = fmaxf(m.x, t.x); m.y = fmaxf(m.y, t.y);
                m.z = fmaxf(m.z, t.z); m.w = fmaxf(m.w, t.w);
            }
        }
        stage[nl][lane * 4 + 0] = fmaxf(m.x, 0.f);
        stage[nl][lane * 4 + 1] = fmaxf(m.y, 0.f);
        stage[nl][lane * 4 + 2] = fmaxf(m.z, 0.f);
        stage[nl][lane * 4 + 3] = fmaxf(m.w, 0.f);
    }
    __syncthreads();
    for (int i = tid; i < 4096; i += 256) {
        int c = i >> 5, nl = i & 31;
        x2[((size_t)(b * RR + c)) * NN + n0 + nl] = stage[nl][c];
    }
    for (int i = tid; i < 4096; i += 256) {
        int nl = i >> 7, c = i & 127;
        x2t[((size_t)(b * NN + n0 + nl)) * RR + c] = stage[nl][c];
    }
}

// ---------------- Laplacian ----------------
__global__ void __launch_bounds__(256) lap_kernel(const float* __restrict__ x2,
                                                  const float* __restrict__ x2t,
                                                  const int* __restrict__ idx,
                                                  float* __restrict__ lap) {
    int g = blockIdx.x, b = blockIdx.y, tid = threadIdx.x;
    __shared__ float srow[NN];
    const float4* src4 = (const float4*)(x2 + ((size_t)(b * RR + g)) * NN);
    for (int i = tid; i < NN / 4; i += 256) ((float4*)srow)[i] = src4[i];
    __syncthreads();
    const int* ib = idx + (size_t)b * NN * KK;
    for (int it = tid; it < 2048; it += 256) {
        int nl = it >> 7, r2 = it & 127;
        int base = nl * NN + r2;
        float sum = 0.f;
#pragma unroll
        for (int j = 0; j < 16; j++) sum += srow[ib[base + (j << 7)]];
        int n = g * 16 + nl;
        size_t o = ((size_t)(b * NN + n)) * RR + r2;
        lap[o] = x2t[o] - sum * 0.0625f;
    }
}

// ---------------- final apply: recompute slot-4 BN consts, then float4 ------------
__global__ void __launch_bounds__(256) final_kernel(float* __restrict__ o,
                                                    const float* __restrict__ P1,
                                                    const float* __restrict__ P2,
                                                    const float* __restrict__ gam,
                                                    const float* __restrict__ bet,
                                                    float M) {
    __shared__ float s5[512], h5[512];
    int tid = threadIdx.x;
    for (int c = tid; c < 512; c += 256) {
        float mean = P1[c] / M;
        float var  = P2[c] / M - mean * mean;
        float s = gam[c] * rsqrtf(var + 1e-5f);
        s5[c] = s; h5[c] = bet[c] - mean * s;
    }
    __syncthreads();
    int i = blockIdx.x * 256 + tid;
    int c = (i >> 9) & 511;
    float s = s5[c], t = h5[c];
    float4 v = ((float4*)o)[i];
    v.x = fmaxf(fmaf(v.x, s, t), 0.f); v.y = fmaxf(fmaf(v.y, s, t), 0.f);
    v.z = fmaxf(fmaf(v.z, s, t), 0.f); v.w = fmaxf(fmaf(v.w, s, t), 0.f);
    ((float4*)o)[i] = v;
}

// ---------------- launch ----------------
extern "C" void kernel_launch(void* const* d_in, const int* in_sizes, int n_in,
                              void* d_out, int out_size) {
    const float* xyz   = (const float*)d_in[0];
    const float* feat  = (const float*)d_in[1];
    const float* w1    = (const float*)d_in[2];
    const float* b1    = (const float*)d_in[3];
    const float* bn1_g = (const float*)d_in[4];
    const float* bn1_b = (const float*)d_in[5];
    const float* fc_w  = (const float*)d_in[6];
    const float* fc_b  = (const float*)d_in[7];
    const float* bng_g = (const float*)d_in[8];
    const float* bng_b = (const float*)d_in[9];
    const float* lu_w  = (const float*)d_in[10];
    const float* lu_b  = (const float*)d_in[11];
    const float* bnl_g = (const float*)d_in[12];
    const float* bnl_b = (const float*)d_in[13];
    const float* w2    = (const float*)d_in[14];
    const float* b2    = (const float*)d_in[15];
    const float* bn2_g = (const float*)d_in[16];
    const float* bn2_b = (const float*)d_in[17];
    const float* w3    = (const float*)d_in[18];
    const float* b3    = (const float*)d_in[19];
    const float* bn3_g = (const float*)d_in[20];
    const float* bn3_b = (const float*)d_in[21];
    float* out = (float*)d_out;

    float *x1, *x2, *x2t, *z, *zt, *lapb, *t, *y, *S1, *S2, *WTp;
    int *idxp, *cntp;
    cudaGetSymbolAddress((void**)&x1,  g_x1);
    cudaGetSymbolAddress((void**)&x2,  g_x2);
    cudaGetSymbolAddress((void**)&x2t, g_x2t);
    cudaGetSymbolAddress((void**)&z,   g_z);
    cudaGetSymbolAddress((void**)&zt,  g_zt);
    cudaGetSymbolAddress((void**)&lapb, g_lap);
    cudaGetSymbolAddress((void**)&t,   g_t);
    cudaGetSymbolAddress((void**)&y,   g_y);
    cudaGetSymbolAddress((void**)&idxp, g_idx);
    cudaGetSymbolAddress((void**)&cntp, g_cnt);
    cudaGetSymbolAddress((void**)&S1,  g_s1);
    cudaGetSymbolAddress((void**)&S2,  g_s2);
    cudaGetSymbolAddress((void**)&WTp, g_wt);

    float Mn = (float)(BB * 2048);
    float Mg = (float)(BB * 16384);

    zero_kernel<<<1, 256>>>();
    tw_kernel<<<128, 256>>>(w1, fc_w, lu_w, w2, w3);
    knn_kernel<<<BB * 8, 256>>>(xyz, idxp);
    cnt_kernel<<<BB, 256>>>(idxp, cntp);

    // mlp1: x1 = w1@feat + b1  (stats -> slot0)
    gemm4_kernel<128, 256, 0, 0, 1, false><<<dim3(16, 1, BB), 256>>>(
        feat, nullptr, WTp, b1, nullptr, nullptr, nullptr, nullptr, 0.f,
        x1, nullptr, S1, S2, nullptr);

    // dsg: z = fc_w @ relu(bn1(x1)) + fc_b (input-BN slot0; stats -> slot1, weighted)
    gemm4_kernel<128, 128, 0, 1, 2, true><<<dim3(16, 1, BB), 256>>>(
        x1, nullptr, WTp + 32768, fc_b, bn1_g, bn1_b, S1, S2, Mn,
        z, zt, S1 + 512, S2 + 512, cntp);
    dsg_max_kernel<<<dim3(64, BB), 256>>>(zt, idxp, x2, x2t,
                                          S1 + 512, S2 + 512, bng_g, bng_b, Mg);

    // laplacian + lu: t = lu_w @ lap + lu_b (stats -> slot2)
    lap_kernel<<<dim3(128, BB), 256>>>(x2, x2t, idxp, lapb);
    gemm4_kernel<128, 128, 2, 0, 1, false><<<dim3(16, 1, BB), 256>>>(
        lapb, nullptr, WTp + 49152, lu_b, nullptr, nullptr, nullptr, nullptr, 0.f,
        t, nullptr, S1 + 1024, S2 + 1024, nullptr);

    // mlp2: y = w2 @ (x2 + relu(bnl(t))) + b2 (input-BN slot2; stats -> slot3)
    gemm4_kernel<256, 128, 0, 2, 1, false><<<dim3(16, 2, BB), 256>>>(
        x2, t, WTp + 65536, b2, bnl_g, bnl_b, S1 + 1024, S2 + 1024, Mn,
        y, nullptr, S1 + 1536, S2 + 1536, nullptr);

    // mlp3: out = w3 @ (relu(bn2(y)) + feat) + b3 (input-BN slot3; stats -> slot4)
    gemm4_kernel<512, 256, 0, 3, 1, false><<<dim3(16, 4, BB), 256>>>(
        y, feat, WTp + 98304, b3, bn2_g, bn2_b, S1 + 1536, S2 + 1536, Mn,
        out, nullptr, S1 + 2048, S2 + 2048, nullptr);

    final_kernel<<<16384, 256>>>(out, S1 + 2048, S2 + 2048, bn3_g, bn3_b, Mn);
}

// round 15
// speedup vs baseline: 1.0420x; 1.0420x over previous
#include <cuda_runtime.h>

#define BB 16
#define NN 2048
#define CC 256
#define RR 128
#define KK 16

// ---------------- scratch ----------------
__device__ float g_x1 [BB*RR*NN];
__device__ float g_x2 [BB*RR*NN];
__device__ float g_x2t[BB*NN*RR];
__device__ float g_zt [BB*NN*RR];
__device__ float g_lap[BB*NN*RR];
__device__ float g_t  [BB*RR*NN];
__device__ float g_y  [BB*CC*NN];
__device__ int   g_idx[BB*NN*KK];
__device__ int   g_cnt[BB*NN];
__device__ float g_s1 [5*512];
__device__ float g_s2 [5*512];
__device__ float g_sc [5*512];
__device__ float g_sh [5*512];

__global__ void zero_kernel() {
    int tid = blockIdx.x * 256 + threadIdx.x;
    int nth = gridDim.x * 256;
    for (int i = tid; i < 5 * 512; i += nth) { g_s1[i] = 0.f; g_s2[i] = 0.f; }
    for (int i = tid; i < BB * NN; i += nth) g_cnt[i] = 0;
}

// ---------------- kNN: bit-exact, register-resident top-16; fused gather counts ---
__global__ void __launch_bounds__(256) knn_kernel(const float* __restrict__ xyz,
                                                  int* __restrict__ idx,
                                                  int* __restrict__ cnt) {
    int b  = blockIdx.x >> 3;
    int q0 = (blockIdx.x & 7) << 8;
    __shared__ float sx[NN], sy[NN], sxx[NN];
    const float* bx = xyz + (size_t)b * 3 * NN;
    for (int i = threadIdx.x; i < NN; i += 256) {
        float xv = bx[i], yv = bx[NN + i];
        sx[i] = xv; sy[i] = yv;
        sxx[i] = __fadd_rn(__fmul_rn(xv, xv), __fmul_rn(yv, yv));
    }
    __syncthreads();
    int q = q0 + threadIdx.x;
    float xq = sx[q], yq = sy[q];
    float xxq = sxx[q];
    float bd[KK]; int bi[KK];
#pragma unroll
    for (int i = 0; i < KK; i++) { bd[i] = 3.4e38f; bi[i] = 0; }
    for (int m = 0; m < NN; m++) {
        float inner = __fmaf_rn(yq, sy[m], __fmul_rn(xq, sx[m]));
        float d = __fadd_rn(__fsub_rn(xxq, __fmul_rn(2.0f, inner)), sxx[m]);
        if (d < bd[KK - 1]) {
            bool p[KK];
#pragma unroll
            for (int i = 0; i < KK; i++) p[i] = (d < bd[i]);
#pragma unroll
            for (int i = KK - 1; i > 0; i--) {
                bd[i] = p[i] ? (p[i - 1] ? bd[i - 1] : d) : bd[i];
                bi[i] = p[i] ? (p[i - 1] ? bi[i - 1] : m) : bi[i];
            }
            if (p[0]) { bd[0] = d; bi[0] = m; }
        }
    }
    int* o = idx + ((size_t)(b * NN + q)) * KK;
#pragma unroll
    for (int i = 0; i < KK; i++) o[i] = bi[i];
    int* cb = cnt + b * NN;
#pragma unroll
    for (int i = 0; i < 8; i++) atomicAdd(&cb[bi[i]], 1);   // DSgroup multiplicity
}

// Granule (16B) XOR swizzle within a 128-float row (pure layout permutation).
__device__ __forceinline__ int swzc(int c) {
    return c ^ (((c >> 5) & 1) << 2);
}

// ---------------- B-tile load with optional fused input transform -----------------
template<int I, int MODE, int TRANS>
__device__ __forceinline__ void load_b(const float* __restrict__ IN,
                                       const float* __restrict__ AUX,
                                       const float* __restrict__ tsc,
                                       const float* __restrict__ tsh,
                                       int b, int q0, int tid, int kb,
                                       float4& v0, float4& v1) {
    if (MODE == 0) {
        int i = tid >> 4, q8 = (tid & 15) * 8;
        size_t off = ((size_t)(b * I + kb + i)) * 2048 + q0 + q8;
        v0 = *(const float4*)(IN + off); v1 = *(const float4*)(IN + off + 4);
        if (TRANS != 0) {
            int c = kb + i;
            float s = tsc[c], h = tsh[c];
            if (TRANS == 1) {
                v0.x = fmaxf(fmaf(v0.x, s, h), 0.f); v0.y = fmaxf(fmaf(v0.y, s, h), 0.f);
                v0.z = fmaxf(fmaf(v0.z, s, h), 0.f); v0.w = fmaxf(fmaf(v0.w, s, h), 0.f);
                v1.x = fmaxf(fmaf(v1.x, s, h), 0.f); v1.y = fmaxf(fmaf(v1.y, s, h), 0.f);
                v1.z = fmaxf(fmaf(v1.z, s, h), 0.f); v1.w = fmaxf(fmaf(v1.w, s, h), 0.f);
            } else {
                float4 a0 = *(const float4*)(AUX + off);
                float4 a1 = *(const float4*)(AUX + off + 4);
                if (TRANS == 2) {                     // x2 + relu(bn(t))
                    v0.x += fmaxf(fmaf(a0.x, s, h), 0.f); v0.y += fmaxf(fmaf(a0.y, s, h), 0.f);
                    v0.z += fmaxf(fmaf(a0.z, s, h), 0.f); v0.w += fmaxf(fmaf(a0.w, s, h), 0.f);
                    v1.x += fmaxf(fmaf(a1.x, s, h), 0.f); v1.y += fmaxf(fmaf(a1.y, s, h), 0.f);
                    v1.z += fmaxf(fmaf(a1.z, s, h), 0.f); v1.w += fmaxf(fmaf(a1.w, s, h), 0.f);
                } else {                              // relu(bn(y)) + feat
                    v0.x = fmaxf(fmaf(v0.x, s, h), 0.f) + a0.x; v0.y = fmaxf(fmaf(v0.y, s, h), 0.f) + a0.y;
                    v0.z = fmaxf(fmaf(v0.z, s, h), 0.f) + a0.z; v0.w = fmaxf(fmaf(v0.w, s, h), 0.f) + a0.w;
                    v1.x = fmaxf(fmaf(v1.x, s, h), 0.f) + a1.x; v1.y = fmaxf(fmaf(v1.y, s, h), 0.f) + a1.y;
                    v1.z = fmaxf(fmaf(v1.z, s, h), 0.f) + a1.z; v1.w = fmaxf(fmaf(v1.w, s, h), 0.f) + a1.w;
                }
            }
        }
    } else {
        int qq = tid >> 1, i8 = (tid & 1) * 8;
        const float* p = IN + ((size_t)(b * 2048 + q0 + qq)) * I + kb + i8;
        v0 = *(const float4*)p; v1 = *(const float4*)(p + 4);
    }
}

// ---------------- pipelined SGEMM (FFMA2 core, swizzled smem, 4x8 warps) ----------
// Per-thread k-chain identical to previous rounds -> bitwise identical outputs.
template<int O, int I, int MODE, int TRANS, int STATS, bool WT, bool OUTW>
__global__ void __launch_bounds__(256, 2) gemm3_kernel(const float* __restrict__ IN,
                                                       const float* __restrict__ AUX,
                                                       const float* __restrict__ W,
                                                       const float* __restrict__ bias,
                                                       const float* __restrict__ tsc,
                                                       const float* __restrict__ tsh,
                                                       float* __restrict__ OUT,
                                                       float* __restrict__ OUT_T,
                                                       float* __restrict__ P1,
                                                       float* __restrict__ P2,
                                                       const int* __restrict__ cnt) {
    __shared__ float sA[2][16][128];
    __shared__ float sB[2][16][128];
    __shared__ float st1[128], st2[128];
    int b  = blockIdx.z;
    int q0 = blockIdx.x * 128;
    int o0 = blockIdx.y * 128;
    int tid = threadIdx.x;
    int w = tid >> 5, lane = tid & 31;
    int ty = (w >> 1) * 4 + (lane >> 3);
    int tx = (w & 1) * 8 + (lane & 7);

    float4 rA0, rA1, rB0, rB1;
    const int oA = tid >> 1, iA = (tid & 1) * 8;
    const int oAs = swzc(oA & ~3) + (oA & 3);

    rA0 = *(const float4*)(W + (size_t)(o0 + oA) * I + iA);
    rA1 = *(const float4*)(W + (size_t)(o0 + oA) * I + iA + 4);
    load_b<I, MODE, TRANS>(IN, AUX, tsc, tsh, b, q0, tid, 0, rB0, rB1);
    {
        float av[8] = {rA0.x, rA0.y, rA0.z, rA0.w, rA1.x, rA1.y, rA1.z, rA1.w};
#pragma unroll
        for (int t = 0; t < 8; t++) sA[0][iA + t][oAs] = av[t];
        if (MODE == 0) {
            int i = tid >> 4, q8 = (tid & 15) * 8;
            *(float4*)&sB[0][i][swzc(q8)] = rB0; *(float4*)&sB[0][i][swzc(q8 + 4)] = rB1;
        } else {
            int qq = tid >> 1, i8 = (tid & 1) * 8;
            int qqs = swzc(qq & ~3) + (qq & 3);
            float bv[8] = {rB0.x, rB0.y, rB0.z, rB0.w, rB1.x, rB1.y, rB1.z, rB1.w};
#pragma unroll
            for (int t = 0; t < 8; t++) sB[0][i8 + t][qqs] = bv[t];
        }
    }
    __syncthreads();

    unsigned long long acc2[8][4];
#pragma unroll
    for (int i = 0; i < 8; i++)
#pragma unroll
        for (int j = 0; j < 4; j++) acc2[i][j] = 0ull;

    const int tyc0 = swzc(ty * 8), tyc1 = swzc(ty * 8 + 4);
    const int txc0 = swzc(tx * 8), txc1 = swzc(tx * 8 + 4);

    int buf = 0;
    for (int kb = 0; kb < I; kb += 16) {
        bool more = (kb + 16) < I;
        if (more) {
            int kn = kb + 16;
            rA0 = *(const float4*)(W + (size_t)(o0 + oA) * I + kn + iA);
            rA1 = *(const float4*)(W + (size_t)(o0 + oA) * I + kn + iA + 4);
            load_b<I, MODE, TRANS>(IN, AUX, tsc, tsh, b, q0, tid, kn, rB0, rB1);
        }
#pragma unroll
        for (int kk = 0; kk < 16; kk++) {
            float a[8];
            *(float4*)&a[0]  = *(const float4*)&sA[buf][kk][tyc0];
            *(float4*)&a[4]  = *(const float4*)&sA[buf][kk][tyc1];
            ulonglong2 bl0 = *(const ulonglong2*)&sB[buf][kk][txc0];
            ulonglong2 bl1 = *(const ulonglong2*)&sB[buf][kk][txc1];
            unsigned long long b2[4] = {bl0.x, bl0.y, bl1.x, bl1.y};
#pragma unroll
            for (int i = 0; i < 8; i++) {
                unsigned long long a2;
                unsigned int au = __float_as_uint(a[i]);
                asm("mov.b64 %0, {%1, %1};" : "=l"(a2) : "r"(au));
#pragma unroll
                for (int j = 0; j < 4; j++)
                    asm("fma.rn.f32x2 %0, %1, %2, %0;" : "+l"(acc2[i][j]) : "l"(a2), "l"(b2[j]));
            }
        }
        if (more) {
            int nb = buf ^ 1;
            float av[8] = {rA0.x, rA0.y, rA0.z, rA0.w, rA1.x, rA1.y, rA1.z, rA1.w};
#pragma unroll
            for (int t = 0; t < 8; t++) sA[nb][iA + t][oAs] = av[t];
            if (MODE == 0) {
                int i = tid >> 4, q8 = (tid & 15) * 8;
                *(float4*)&sB[nb][i][swzc(q8)] = rB0; *(float4*)&sB[nb][i][swzc(q8 + 4)] = rB1;
            } else {
                int qq = tid >> 1, i8 = (tid & 1) * 8;
                int qqs = swzc(qq & ~3) + (qq & 3);
                float bv[8] = {rB0.x, rB0.y, rB0.z, rB0.w, rB1.x, rB1.y, rB1.z, rB1.w};
#pragma unroll
                for (int t = 0; t < 8; t++) sB[nb][i8 + t][qqs] = bv[t];
            }
        }
        __syncthreads();
        buf ^= 1;
    }

    float acc[8][8];
#pragma unroll
    for (int i = 0; i < 8; i++)
#pragma unroll
        for (int j = 0; j < 4; j++) {
            unsigned int lo, hi;
            asm("mov.b64 {%0, %1}, %2;" : "=r"(lo), "=r"(hi) : "l"(acc2[i][j]));
            acc[i][2 * j]     = __uint_as_float(lo);
            acc[i][2 * j + 1] = __uint_as_float(hi);
        }

    float bv[8];
#pragma unroll
    for (int i = 0; i < 8; i++) bv[i] = bias[o0 + ty * 8 + i];
    if (OUTW) {
#pragma unroll
        for (int i = 0; i < 8; i++) {
            float* orow = OUT + ((size_t)(b * O + o0 + ty * 8 + i)) * 2048 + q0 + tx * 8;
            float4 v0 = {acc[i][0] + bv[i], acc[i][1] + bv[i], acc[i][2] + bv[i], acc[i][3] + bv[i]};
            float4 v1 = {acc[i][4] + bv[i], acc[i][5] + bv[i], acc[i][6] + bv[i], acc[i][7] + bv[i]};
            *(float4*)orow = v0; *(float4*)(orow + 4) = v1;
        }
    }
    if (WT) {
#pragma unroll
        for (int j = 0; j < 8; j++) {
            float* trow = OUT_T + ((size_t)(b * 2048 + q0 + tx * 8 + j)) * O + o0 + ty * 8;
            float4 v0 = {acc[0][j] + bv[0], acc[1][j] + bv[1], acc[2][j] + bv[2], acc[3][j] + bv[3]};
            float4 v1 = {acc[4][j] + bv[4], acc[5][j] + bv[5], acc[6][j] + bv[6], acc[7][j] + bv[7]};
            *(float4*)trow = v0; *(float4*)(trow + 4) = v1;
        }
    }
    if (STATS != 0) {
        if (tid < 128) { st1[tid] = 0.f; st2[tid] = 0.f; }
        __syncthreads();
        float wj[8];
#pragma unroll
        for (int j = 0; j < 8; j++)
            wj[j] = (STATS == 2) ? (float)cnt[(size_t)b * 2048 + q0 + tx * 8 + j] : 1.f;
#pragma unroll
        for (int i = 0; i < 8; i++) {
            float ls = 0.f, ls2 = 0.f;
#pragma unroll
            for (int j = 0; j < 8; j++) {
                float val = acc[i][j] + bv[i];
                float wv = wj[j] * val;
                ls += wv; ls2 = fmaf(wv, val, ls2);
            }
            atomicAdd(&st1[ty * 8 + i], ls);
            atomicAdd(&st2[ty * 8 + i], ls2);
        }
        __syncthreads();
        if (tid < 128) {
            atomicAdd(&P1[o0 + tid], st1[tid]);
            atomicAdd(&P2[o0 + tid], st2[tid]);
        }
    }
}

// ---------------- BN finalize ----------------
__global__ void bn_fin_kernel(const float* __restrict__ P1, const float* __restrict__ P2,
                              const float* __restrict__ gam, const float* __restrict__ bet,
                              float* __restrict__ sc, float* __restrict__ sh, float M) {
    int c = threadIdx.x;
    float mean = P1[c] / M;
    float var  = P2[c] / M - mean * mean;
    float s = gam[c] * rsqrtf(var + 1e-5f);
    sc[c] = s; sh[c] = bet[c] - mean * s;
}

// ---------------- DSgroup: gather zt rows, BN+max8+ReLU -> x2, x2t ----------------
__global__ void __launch_bounds__(256) dsg_max_kernel(const float* __restrict__ zt,
                                                      const int* __restrict__ idx,
                                                      float* __restrict__ x2,
                                                      float* __restrict__ x2t,
                                                      const float* __restrict__ scp,
                                                      const float* __restrict__ shp) {
    int b = blockIdx.y, n0 = blockIdx.x * 32;
    int tid = threadIdx.x, w = tid >> 5, lane = tid & 31;
    __shared__ float stage[32][129];
    float4 sc = ((const float4*)scp)[lane], sh = ((const float4*)shp)[lane];
#pragma unroll
    for (int phase = 0; phase < 4; phase++) {
        int nl = phase * 8 + w;
        int n  = n0 + nl;
        int src = 0;
        if (lane < 8) {
            int p = lane * NN + n;
            src = idx[((size_t)(b * NN + (p >> 3))) * KK + (p & 7)];
        }
        float4 m;
#pragma unroll
        for (int j = 0; j < 8; j++) {
            int s = __shfl_sync(0xffffffffu, src, j);
            float4 v = *(const float4*)(zt + ((size_t)(b * NN + s)) * RR + lane * 4);
            float4 t;
            t.x = fmaf(v.x, sc.x, sh.x); t.y = fmaf(v.y, sc.y, sh.y);
            t.z = fmaf(v.z, sc.z, sh.z); t.w = fmaf(v.w, sc.w, sh.w);
            if (j == 0) m = t;
            else {
                m.x = fmaxf(m.x, t.x); m.y = fmaxf(m.y, t.y);
                m.z = fmaxf(m.z, t.z); m.w = fmaxf(m.w, t.w);
            }
        }
        stage[nl][lane * 4 + 0] = fmaxf(m.x, 0.f);
        stage[nl][lane * 4 + 1] = fmaxf(m.y, 0.f);
        stage[nl][lane * 4 + 2] = fmaxf(m.z, 0.f);
        stage[nl][lane * 4 + 3] = fmaxf(m.w, 0.f);
    }
    __syncthreads();
    for (int i = tid; i < 4096; i += 256) {
        int c = i >> 5, nl = i & 31;
        x2[((size_t)(b * RR + c)) * NN + n0 + nl] = stage[nl][c];
    }
    for (int i = tid; i < 4096; i += 256) {
        int nl = i >> 7, c = i & 127;
        x2t[((size_t)(b * NN + n0 + nl)) * RR + c] = stage[nl][c];
    }
}

// ---------------- Laplacian ----------------
__global__ void __launch_bounds__(256) lap_kernel(const float* __restrict__ x2,
                                                  const float* __restrict__ x2t,
                                                  const int* __restrict__ idx,
                                                  float* __restrict__ lap) {
    int g = blockIdx.x, b = blockIdx.y, tid = threadIdx.x;
    __shared__ float srow[NN];
    const float4* src4 = (const float4*)(x2 + ((size_t)(b * RR + g)) * NN);
    for (int i = tid; i < NN / 4; i += 256) ((float4*)srow)[i] = src4[i];
    __syncthreads();
    const int* ib = idx + (size_t)b * NN * KK;
    for (int it = tid; it < 2048; it += 256) {
        int nl = it >> 7, r2 = it & 127;
        int base = nl * NN + r2;
        float sum = 0.f;
#pragma unroll
        for (int j = 0; j < 16; j++) sum += srow[ib[base + (j << 7)]];
        int n = g * 16 + nl;
        size_t o = ((size_t)(b * NN + n)) * RR + r2;
        lap[o] = x2t[o] - sum * 0.0625f;
    }
}

// ---------------- final apply (float4) ----------------
__global__ void __launch_bounds__(256) final_kernel(float* __restrict__ o,
                                                    const float* __restrict__ sc,
                                                    const float* __restrict__ sh) {
    int i = blockIdx.x * 256 + threadIdx.x;
    int c = (i >> 9) & 511;
    float s = sc[c], t = sh[c];
    float4 v = ((float4*)o)[i];
    v.x = fmaxf(fmaf(v.x, s, t), 0.f); v.y = fmaxf(fmaf(v.y, s, t), 0.f);
    v.z = fmaxf(fmaf(v.z, s, t), 0.f); v.w = fmaxf(fmaf(v.w, s, t), 0.f);
    ((float4*)o)[i] = v;
}

// ---------------- launch ----------------
extern "C" void kernel_launch(void* const* d_in, const int* in_sizes, int n_in,
                              void* d_out, int out_size) {
    const float* xyz   = (const float*)d_in[0];
    const float* feat  = (const float*)d_in[1];
    const float* w1    = (const float*)d_in[2];
    const float* b1    = (const float*)d_in[3];
    const float* bn1_g = (const float*)d_in[4];
    const float* bn1_b = (const float*)d_in[5];
    const float* fc_w  = (const float*)d_in[6];
    const float* fc_b  = (const float*)d_in[7];
    const float* bng_g = (const float*)d_in[8];
    const float* bng_b = (const float*)d_in[9];
    const float* lu_w  = (const float*)d_in[10];
    const float* lu_b  = (const float*)d_in[11];
    const float* bnl_g = (const float*)d_in[12];
    const float* bnl_b = (const float*)d_in[13];
    const float* w2    = (const float*)d_in[14];
    const float* b2    = (const float*)d_in[15];
    const float* bn2_g = (const float*)d_in[16];
    const float* bn2_b = (const float*)d_in[17];
    const float* w3    = (const float*)d_in[18];
    const float* b3    = (const float*)d_in[19];
    const float* bn3_g = (const float*)d_in[20];
    const float* bn3_b = (const float*)d_in[21];
    float* out = (float*)d_out;

    float *x1, *x2, *x2t, *zt, *lapb, *t, *y, *S1, *S2, *SC, *SH;
    int *idxp, *cntp;
    cudaGetSymbolAddress((void**)&x1,  g_x1);
    cudaGetSymbolAddress((void**)&x2,  g_x2);
    cudaGetSymbolAddress((void**)&x2t, g_x2t);
    cudaGetSymbolAddress((void**)&zt,  g_zt);
    cudaGetSymbolAddress((void**)&lapb, g_lap);
    cudaGetSymbolAddress((void**)&t,   g_t);
    cudaGetSymbolAddress((void**)&y,   g_y);
    cudaGetSymbolAddress((void**)&idxp, g_idx);
    cudaGetSymbolAddress((void**)&cntp, g_cnt);
    cudaGetSymbolAddress((void**)&S1,  g_s1);
    cudaGetSymbolAddress((void**)&S2,  g_s2);
    cudaGetSymbolAddress((void**)&SC,  g_sc);
    cudaGetSymbolAddress((void**)&SH,  g_sh);

    zero_kernel<<<32, 256>>>();
    knn_kernel<<<BB * 8, 256>>>(xyz, idxp, cntp);

    gemm3_kernel<128, 256, 0, 0, 1, false, true><<<dim3(16, 1, BB), 256>>>(
        feat, nullptr, w1, b1, nullptr, nullptr, x1, nullptr, S1, S2, nullptr);
    bn_fin_kernel<<<1, 128>>>(S1, S2, bn1_g, bn1_b, SC, SH, (float)(BB * 2048));

    gemm3_kernel<128, 128, 0, 1, 2, true, false><<<dim3(16, 1, BB), 256>>>(
        x1, nullptr, fc_w, fc_b, SC, SH, nullptr, zt, S1 + 512, S2 + 512, cntp);
    bn_fin_kernel<<<1, 128>>>(S1 + 512, S2 + 512, bng_g, bng_b, SC + 512, SH + 512,
                              (float)(BB * 16384));
    dsg_max_kernel<<<dim3(64, BB), 256>>>(zt, idxp, x2, x2t, SC + 512, SH + 512);

    lap_kernel<<<dim3(128, BB), 256>>>(x2, x2t, idxp, lapb);
    gemm3_kernel<128, 128, 2, 0, 1, false, true><<<dim3(16, 1, BB), 256>>>(
        lapb, nullptr, lu_w, lu_b, nullptr, nullptr, t, nullptr, S1 + 1024, S2 + 1024, nullptr);
    bn_fin_kernel<<<1, 128>>>(S1 + 1024, S2 + 1024, bnl_g, bnl_b, SC + 1024, SH + 1024,
                              (float)(BB * 2048));

    gemm3_kernel<256, 128, 0, 2, 1, false, true><<<dim3(16, 2, BB), 256>>>(
        x2, t, w2, b2, SC + 1024, SH + 1024, y, nullptr, S1 + 1536, S2 + 1536, nullptr);
    bn_fin_kernel<<<1, 256>>>(S1 + 1536, S2 + 1536, bn2_g, bn2_b, SC + 1536, SH + 1536,
                              (float)(BB * 2048));

    gemm3_kernel<512, 256, 0, 3, 1, false, true><<<dim3(16, 4, BB), 256>>>(
        y, feat, w3, b3, SC + 1536, SH + 1536, out, nullptr, S1 + 2048, S2 + 2048, nullptr);
    bn_fin_kernel<<<1, 512>>>(S1 + 2048, S2 + 2048, bn3_g, bn3_b, SC + 2048, SH + 2048,
                              (float)(BB * 2048));
    final_kernel<<<16384, 256>>>(out, SC + 2048, SH + 2048);
}